// round 5
// baseline (speedup 1.0000x reference)
#include <cuda_runtime.h>

// HysteresisThresholding 2048x2048. Three kernels:
//  1) pack:  thresholds (low/high outputs) + bit-packed weak/strong masks
//  2) flood: persistent, 1 block/SM band-local smem convergence, light
//            flag-array grid barrier between passes
//  3) final: active ? thin : 0
// Kernel boundaries double as free global barriers.

#define H_IMG 2048
#define W_IMG 2048
#define WX 64
#define QX 512
#define N_WORDS (H_IMG * WX)
#define N_PIX (H_IMG * W_IMG)
#define N_QUAD (N_PIX / 4)
#define LOW_T 0.3f
#define HIGH_T 0.7f
#define MAX_PASS 256
#define MAX_ROWS 16
#define NT 1024

__device__ unsigned g_active[N_WORDS];
__device__ unsigned g_w1[N_WORDS];
__device__ unsigned g_w2[N_WORDS];
__device__ unsigned g_changed[MAX_PASS];
__device__ volatile unsigned g_arrive[256];
__device__ volatile unsigned g_release;

// ---------------- kernel 1: thresholds + mask pack ----------------
__global__ void __launch_bounds__(256)
pack_kernel(const float4* __restrict__ thin4, float* __restrict__ out) {
    int qg = blockIdx.x * 256 + threadIdx.x;
    unsigned lane = threadIdx.x & 31u;
    const unsigned nsh   = (lane & 7u) * 4u;
    const unsigned gmask = 0xFFu << (lane & 24u);

    float4* low4  = (float4*)out;
    float4* high4 = (float4*)(out + N_PIX);

    float4 v = thin4[qg];
    float4 lo, hi;
    lo.x = (v.x < LOW_T)  ? 0.0f : v.x;  hi.x = (v.x < HIGH_T) ? 0.0f : v.x;
    lo.y = (v.y < LOW_T)  ? 0.0f : v.y;  hi.y = (v.y < HIGH_T) ? 0.0f : v.y;
    lo.z = (v.z < LOW_T)  ? 0.0f : v.z;  hi.z = (v.z < HIGH_T) ? 0.0f : v.z;
    lo.w = (v.w < LOW_T)  ? 0.0f : v.w;  hi.w = (v.w < HIGH_T) ? 0.0f : v.w;
    low4[qg]  = lo;
    high4[qg] = hi;

    unsigned nw = (v.x >= LOW_T ? 1u : 0u) | (v.y >= LOW_T ? 2u : 0u)
                | (v.z >= LOW_T ? 4u : 0u) | (v.w >= LOW_T ? 8u : 0u);
    unsigned ns = (v.x >= HIGH_T ? 1u : 0u) | (v.y >= HIGH_T ? 2u : 0u)
                | (v.z >= HIGH_T ? 4u : 0u) | (v.w >= HIGH_T ? 8u : 0u);
    unsigned wk = __reduce_or_sync(gmask, nw << nsh);
    unsigned ac = __reduce_or_sync(gmask, ns << nsh);

    if ((lane & 7u) == 0u) {
        int gw = qg >> 3;
        int r = gw >> 6, wx = gw & 63;
        unsigned t1c = (wx == 0) ? 0xFFFFFFFEu : (wx == WX - 1) ? 0x3FFFFFFFu : 0xFFFFFFFFu;
        unsigned t1r = (r >= 1 && r <= H_IMG - 3) ? 0xFFFFFFFFu : 0u;
        unsigned t2c = (wx == 0) ? 0xFFFFFFFCu : (wx == WX - 1) ? 0x1FFFFFFFu : 0xFFFFFFFFu;
        unsigned t2r = (r >= 2 && r <= H_IMG - 4) ? 0xFFFFFFFFu : 0u;
        g_w1[gw]     = wk & t1c & t1r;
        g_w2[gw]     = wk & t2c & t2r;
        g_active[gw] = ac;
    }

    if (blockIdx.x == 0) {
        if (threadIdx.x < MAX_PASS) g_changed[threadIdx.x] = 0u;
        if (threadIdx.x < 256) g_arrive[threadIdx.x] = 0u;
        if (threadIdx.x == 0) g_release = 0u;
    }
}

// ---------------- light flag-array grid barrier ----------------
__device__ __forceinline__ void grid_barrier(int bid, int tid, unsigned nblocks, unsigned gen) {
    __syncthreads();
    if (tid == 0) { __threadfence(); g_arrive[bid] = gen; }
    if (bid == 0) {
        if (tid < (int)nblocks) { while (g_arrive[tid] < gen) __nanosleep(32); }
        __syncthreads();
        if (tid == 0) { __threadfence(); g_release = gen; }
    }
    if (tid == 0) {
        while (g_release < gen) __nanosleep(32);
        __threadfence();
    }
    __syncthreads();
}

// ---------------- kernel 2: band-local flood fill ----------------
__global__ void __launch_bounds__(NT, 1)
flood_kernel(int rows_per, unsigned nblocks) {
    __shared__ unsigned s_act[(MAX_ROWS + 4) * WX];
    __shared__ unsigned s_w1[MAX_ROWS * WX];
    __shared__ unsigned s_w2[MAX_ROWS * WX];

    const int tid = threadIdx.x;
    const int bid = blockIdx.x;
    const int r0  = bid * rows_per;
    const int nrows  = max(0, min(H_IMG - r0, rows_per));
    const int nwords = nrows * WX;

    for (int i = tid; i < (MAX_ROWS + 4) * WX; i += NT) s_act[i] = 0u;
    if (tid < nwords) {
        s_w1[tid] = g_w1[r0 * WX + tid];
        s_w2[tid] = g_w2[r0 * WX + tid];
        s_act[((tid >> 6) + 2) * WX + (tid & 63)] = g_active[r0 * WX + tid];
    }
    __syncthreads();

    unsigned gen = 0;
    for (int pass = 0; pass < MAX_PASS; pass++) {
        // reload 4 halo rows
        for (int i = tid; i < 4 * WX; i += NT) {
            int hr = i >> 6, wx = i & 63;
            int gr = (hr < 2) ? (r0 - 2 + hr) : (r0 + nrows + (hr - 2));
            int sr = (hr < 2) ? hr : (nrows + hr);
            unsigned v = 0u;
            if (gr >= 0 && gr < H_IMG) v = __ldcg(&g_active[gr * WX + wx]);
            s_act[sr * WX + wx] = v;
        }
        __syncthreads();

        bool band_changed = false;
        for (;;) {
            bool ch = false;
            if (tid < nwords) {
                int wx = tid & 63;
                int sr = (tid >> 6) + 2;
                unsigned c  = s_act[sr * WX + wx];
                unsigned w1 = s_w1[tid];
                unsigned w2 = s_w2[tid];
                unsigned todo = (w1 | w2) & ~c;
                if (todo) {
                    auto S = [&](int r_, int x_) -> unsigned {
                        return ((unsigned)x_ < (unsigned)WX) ? s_act[r_ * WX + x_] : 0u;
                    };
                    unsigned l  = S(sr, wx - 1),      rr = S(sr, wx + 1);
                    unsigned u1 = S(sr - 1, wx), u1l = S(sr - 1, wx - 1), u1r = S(sr - 1, wx + 1);
                    unsigned d1 = S(sr + 1, wx), d1l = S(sr + 1, wx - 1), d1r = S(sr + 1, wx + 1);
                    unsigned conn1 =
                          u1 | __funnelshift_l(u1l, u1, 1) | __funnelshift_r(u1, u1r, 1)
                        |      __funnelshift_l(l,   c,  1) | __funnelshift_r(c,  rr,  1)
                        | d1 | __funnelshift_l(d1l, d1, 1) | __funnelshift_r(d1, d1r, 1);
                    unsigned nw = c | (w1 & conn1);
                    if (w2 & ~nw) {
                        unsigned u2 = S(sr - 2, wx), u2l = S(sr - 2, wx - 1), u2r = S(sr - 2, wx + 1);
                        unsigned d2 = S(sr + 2, wx), d2l = S(sr + 2, wx - 1), d2r = S(sr + 2, wx + 1);
                        unsigned conn2 =
                              u2 | __funnelshift_l(u2l, u2, 2) | __funnelshift_r(u2, u2r, 2)
                            |      __funnelshift_l(l,   c,  2) | __funnelshift_r(c,  rr,  2)
                            | d2 | __funnelshift_l(d2l, d2, 2) | __funnelshift_r(d2, d2r, 2);
                        nw |= w2 & conn2;
                    }
                    #pragma unroll
                    for (int k = 0; k < 5; k++) {
                        unsigned sp = nw;
                        nw |= (w1 & ((sp << 1) | (sp >> 1)))
                            | (w2 & ((sp << 2) | (sp >> 2)));
                    }
                    if (nw != c) { s_act[sr * WX + wx] = nw; ch = true; }
                }
            }
            if (!__syncthreads_or(ch ? 1 : 0)) break;
            band_changed = true;
        }

        if (band_changed) {
            if (tid < nwords)
                __stcg(&g_active[r0 * WX + tid],
                       s_act[((tid >> 6) + 2) * WX + (tid & 63)]);
            if (tid == 0) __stcg(&g_changed[pass], 1u);
        }

        gen++;
        grid_barrier(bid, tid, nblocks, gen);
        if (*(volatile unsigned*)&g_changed[pass] == 0u) break;
    }
}

// ---------------- kernel 3: final output ----------------
__global__ void __launch_bounds__(256)
final_kernel(const float4* __restrict__ thin4, float* __restrict__ out) {
    int qg = blockIdx.x * 256 + threadIdx.x;
    float4* final4 = (float4*)(out + 2 * N_PIX);
    unsigned word = __ldcg(&g_active[qg >> 3]);
    unsigned bits = word >> ((qg & 7u) * 4u);
    float4 v = thin4[qg];
    float4 f;
    f.x = (bits & 1u) ? v.x : 0.0f;
    f.y = (bits & 2u) ? v.y : 0.0f;
    f.z = (bits & 4u) ? v.z : 0.0f;
    f.w = (bits & 8u) ? v.w : 0.0f;
    final4[qg] = f;
}

extern "C" void kernel_launch(void* const* d_in, const int* in_sizes, int n_in,
                              void* d_out, int out_size) {
    const float* thin = (const float*)d_in[0];
    float* out = (float*)d_out;
    (void)in_sizes; (void)n_in; (void)out_size;

    int dev = 0;
    cudaGetDevice(&dev);
    int nsm = 0;
    cudaDeviceGetAttribute(&nsm, cudaDevAttrMultiProcessorCount, dev);
    if (nsm <= 0) nsm = 148;

    int rows_per = (H_IMG + nsm - 1) / nsm;
    if (rows_per > MAX_ROWS) rows_per = MAX_ROWS;
    unsigned fgrid = (unsigned)((H_IMG + rows_per - 1) / rows_per);

    pack_kernel<<<N_QUAD / 256, 256>>>((const float4*)thin, out);
    flood_kernel<<<fgrid, NT>>>(rows_per, fgrid);
    final_kernel<<<N_QUAD / 256, 256>>>((const float4*)thin, out);
}